// round 1
// baseline (speedup 1.0000x reference)
#include <cuda_runtime.h>

// ComposeTransform: out = u2 + trilinear_sample(u1, grid + u2)
// Shapes: warp1, warp2, out all [B=2, D=160, H=160, W=160, C=3] fp32.

#define Bc  2
#define Dd  160
#define Hh  160
#define Ww  160
#define HW  (Hh * Ww)
#define DHW (Dd * HW)
#define NVOX (Bc * DHW)

#define TPB 256

__global__ __launch_bounds__(TPB)
void compose_transform_kernel(const float* __restrict__ w1,
                              const float* __restrict__ w2,
                              float* __restrict__ out)
{
    __shared__ float s[TPB * 3];  // 3 KB staging buffer (reused for in + out)

    const int t    = threadIdx.x;
    const int vox0 = blockIdx.x * TPB;

    // ---- Stage warp2 for this block as float4 (fully coalesced 128-bit) ----
    // base float offset = vox0*3 = blockIdx*768, divisible by 16B. TPB*3/4 = 192 vecs.
    {
        const float4* __restrict__ w2v =
            reinterpret_cast<const float4*>(w2 + (size_t)vox0 * 3);
        float4* sv = reinterpret_cast<float4*>(s);
        if (t < (TPB * 3) / 4) sv[t] = w2v[t];
    }
    __syncthreads();

    // stride-3 shared reads: gcd(3,32)=1 -> conflict-free
    const float u2x = s[t * 3 + 0];
    const float u2y = s[t * 3 + 1];
    const float u2z = s[t * 3 + 2];

    // ---- Decompose voxel index (z innermost -> warp-contiguous gathers) ----
    const int vox = vox0 + t;
    const int b   = vox / DHW;
    int r         = vox - b * DHW;
    const int x   = r / HW;
    r            -= x * HW;
    const int y   = r / Ww;
    const int z   = r - y * Ww;

    // ---- Sample location, border-clipped ----
    float lx = fminf(fmaxf((float)x + u2x, 0.0f), (float)(Dd - 1));
    float ly = fminf(fmaxf((float)y + u2y, 0.0f), (float)(Hh - 1));
    float lz = fminf(fmaxf((float)z + u2z, 0.0f), (float)(Ww - 1));

    const float fx = floorf(lx), fy = floorf(ly), fz = floorf(lz);
    const int ix0 = (int)fx, iy0 = (int)fy, iz0 = (int)fz;
    const float wx = lx - fx, wy = ly - fy, wz = lz - fz;
    const int ix1 = min(ix0 + 1, Dd - 1);
    const int iy1 = min(iy0 + 1, Hh - 1);
    const int iz1 = min(iz0 + 1, Ww - 1);

    const float* __restrict__ base = w1 + (size_t)b * (size_t)DHW * 3;

    const float wx0 = 1.0f - wx, wy0 = 1.0f - wy, wz0 = 1.0f - wz;

    float ox = 0.0f, oy = 0.0f, oz = 0.0f;

#pragma unroll
    for (int cx = 0; cx < 2; ++cx) {
        const int   ix  = cx ? ix1 : ix0;
        const float wxx = cx ? wx : wx0;
#pragma unroll
        for (int cy = 0; cy < 2; ++cy) {
            const int   iy  = cy ? iy1 : iy0;
            const float wxy = wxx * (cy ? wy : wy0);
#pragma unroll
            for (int cz = 0; cz < 2; ++cz) {
                const int   iz = cz ? iz1 : iz0;
                const float wgt = wxy * (cz ? wz : wz0);
                const int off = ((ix * Hh + iy) * Ww + iz) * 3;
                ox = fmaf(__ldg(base + off + 0), wgt, ox);
                oy = fmaf(__ldg(base + off + 1), wgt, oy);
                oz = fmaf(__ldg(base + off + 2), wgt, oz);
            }
        }
    }

    // ---- Stage result, then write out as float4 ----
    __syncthreads();  // all shared reads of u2 are done (values in registers)
    s[t * 3 + 0] = u2x + ox;
    s[t * 3 + 1] = u2y + oy;
    s[t * 3 + 2] = u2z + oz;
    __syncthreads();

    {
        float4* __restrict__ ov =
            reinterpret_cast<float4*>(out + (size_t)vox0 * 3);
        const float4* sv = reinterpret_cast<const float4*>(s);
        if (t < (TPB * 3) / 4) ov[t] = sv[t];
    }
}

extern "C" void kernel_launch(void* const* d_in, const int* in_sizes, int n_in,
                              void* d_out, int out_size)
{
    const float* warp1 = (const float*)d_in[0];
    const float* warp2 = (const float*)d_in[1];
    float* out = (float*)d_out;

    const int blocks = NVOX / TPB;  // 8,192,000 / 256 = 32,000
    compose_transform_kernel<<<blocks, TPB>>>(warp1, warp2, out);
}

// round 2
// speedup vs baseline: 1.1609x; 1.1609x over previous
#include <cuda_runtime.h>

// out = u2 + trilinear(u1, grid + u2), [B=2,160,160,160,3] fp32.
// Shared-memory tile for the divergent trilinear gathers; rare out-of-halo
// threads fall back to global gathers (exact same math).

#define Dd 160
#define Hh 160
#define Ww 160
#define HW  (Hh * Ww)
#define DHW (Dd * HW)

#define TX 10
#define TY 16
#define TZ 32
#define HALO 4
#define SX (TX + 2 * HALO)   // 18
#define SY (TY + 2 * HALO)   // 24
#define SZ (TZ + 2 * HALO)   // 40
#define RS (SZ * 3)          // 120 floats per (x,y) row in the tile
#define SMEM_FLOATS (SX * SY * RS)   // 51840 floats = 207,360 B
#define TPB 512
#define NWARP (TPB / 32)     // 16

extern __shared__ float s[];

__global__ __launch_bounds__(TPB, 1)
void compose_tile_kernel(const float* __restrict__ w1,
                         const float* __restrict__ w2,
                         float* __restrict__ out)
{
    const int x0 = blockIdx.x * TX;
    const int y0 = blockIdx.y * TY;
    const int b  = blockIdx.z / 5;
    const int z0 = (blockIdx.z % 5) * TZ;

    const int t    = threadIdx.x;
    const int lane = t & 31;
    const int wrp  = t >> 5;

    const float* __restrict__ w1b = w1 + (size_t)b * (size_t)DHW * 3;

    // ---- Cooperative tile load: w1[b, x0-4..x0+TX+3, y0-4.., z0-4..] -> smem ----
    // Row start float offset = row*480 + zlo*3; zlo % 4 == 0 always -> 16B aligned.
    {
        const int zlo  = max(z0 - HALO, 0);
        const int zhi  = min(z0 + TZ + HALO, Ww);
        const int nvec = (zhi - zlo) * 3 / 4;         // 27 or 30 float4 per row
        const int dsto = (zlo - (z0 - HALO)) * 3;     // 0 or 12 floats (16B aligned)

        for (int r = wrp; r < SX * SY; r += NWARP) {
            const int hx = r / SY;
            const int hy = r - hx * SY;
            const int cx = x0 - HALO + hx;
            const int cy = y0 - HALO + hy;
            if ((unsigned)cx < (unsigned)Dd && (unsigned)cy < (unsigned)Hh &&
                lane < nvec) {
                const float4* __restrict__ src = reinterpret_cast<const float4*>(
                    w1b + ((size_t)(cx * Hh + cy) * Ww + zlo) * 3);
                float4* dst = reinterpret_cast<float4*>(
                    s + (hx * SY + hy) * RS + dsto);
                dst[lane] = src[lane];
            }
        }
    }
    __syncthreads();

    // ---- Compute: lane = z (coalesced w2/out), warp = y row ----
    const int hz = lane;            // 0..31
    const int hy = wrp;             // 0..15
    const int y  = y0 + hy;
    const int z  = z0 + hz;

#pragma unroll 2
    for (int dxi = 0; dxi < TX; ++dxi) {
        const int x = x0 + dxi;
        const int f = (((b * Dd + x) * Hh + y) * Ww + z) * 3;

        const float u2x = __ldg(w2 + f + 0);
        const float u2y = __ldg(w2 + f + 1);
        const float u2z = __ldg(w2 + f + 2);

        float lx = fminf(fmaxf((float)x + u2x, 0.0f), (float)(Dd - 1));
        float ly = fminf(fmaxf((float)y + u2y, 0.0f), (float)(Hh - 1));
        float lz = fminf(fmaxf((float)z + u2z, 0.0f), (float)(Ww - 1));

        const float fx = floorf(lx), fy = floorf(ly), fz = floorf(lz);
        const int ix0 = (int)fx, iy0 = (int)fy, iz0 = (int)fz;
        const float wx = lx - fx, wy = ly - fy, wz = lz - fz;
        const float wx0 = 1.0f - wx, wy0 = 1.0f - wy, wz0 = 1.0f - wz;

        const int ix1 = min(ix0 + 1, Dd - 1);
        const int iy1 = min(iy0 + 1, Hh - 1);
        const int iz1 = min(iz0 + 1, Ww - 1);

        const int sx0 = ix0 - (x0 - HALO);
        const int sy0 = iy0 - (y0 - HALO);
        const int sz0 = iz0 - (z0 - HALO);

        float ox, oy, oz;

        const bool fast = ((unsigned)sx0 <= (unsigned)(SX - 2)) &&
                          ((unsigned)sy0 <= (unsigned)(SY - 2)) &&
                          ((unsigned)sz0 <= (unsigned)(SZ - 2));
        if (fast) {
            const int sx1 = ix1 - (x0 - HALO);
            const int sy1 = iy1 - (y0 - HALO);
            const int za  = sz0 * 3;
            const int zb  = (iz1 - (z0 - HALO)) * 3;

            const float* p00 = s + (sx0 * SY + sy0) * RS;
            const float* p01 = s + (sx0 * SY + sy1) * RS;
            const float* p10 = s + (sx1 * SY + sy0) * RS;
            const float* p11 = s + (sx1 * SY + sy1) * RS;

            float acc[3];
#pragma unroll
            for (int c = 0; c < 3; ++c) {
                const float v00 = p00[za + c] * wz0 + p00[zb + c] * wz;
                const float v01 = p01[za + c] * wz0 + p01[zb + c] * wz;
                const float v10 = p10[za + c] * wz0 + p10[zb + c] * wz;
                const float v11 = p11[za + c] * wz0 + p11[zb + c] * wz;
                acc[c] = (v00 * wy0 + v01 * wy) * wx0 +
                         (v10 * wy0 + v11 * wy) * wx;
            }
            ox = acc[0]; oy = acc[1]; oz = acc[2];
        } else {
            // Rare slow path: direct global gather (≈0.02% of threads).
            float a0 = 0.f, a1 = 0.f, a2 = 0.f;
#pragma unroll
            for (int cx = 0; cx < 2; ++cx) {
                const int   ix  = cx ? ix1 : ix0;
                const float wxx = cx ? wx : wx0;
#pragma unroll
                for (int cy = 0; cy < 2; ++cy) {
                    const int   iy  = cy ? iy1 : iy0;
                    const float wxy = wxx * (cy ? wy : wy0);
#pragma unroll
                    for (int cz = 0; cz < 2; ++cz) {
                        const int   iz  = cz ? iz1 : iz0;
                        const float wgt = wxy * (cz ? wz : wz0);
                        const int off = ((ix * Hh + iy) * Ww + iz) * 3;
                        a0 = fmaf(__ldg(w1b + off + 0), wgt, a0);
                        a1 = fmaf(__ldg(w1b + off + 1), wgt, a1);
                        a2 = fmaf(__ldg(w1b + off + 2), wgt, a2);
                    }
                }
            }
            ox = a0; oy = a1; oz = a2;
        }

        out[f + 0] = u2x + ox;
        out[f + 1] = u2y + oy;
        out[f + 2] = u2z + oz;
    }
}

extern "C" void kernel_launch(void* const* d_in, const int* in_sizes, int n_in,
                              void* d_out, int out_size)
{
    const float* warp1 = (const float*)d_in[0];
    const float* warp2 = (const float*)d_in[1];
    float* out = (float*)d_out;

    static const size_t smem_bytes = SMEM_FLOATS * sizeof(float);  // 207,360
    cudaFuncSetAttribute(compose_tile_kernel,
                         cudaFuncAttributeMaxDynamicSharedMemorySize,
                         (int)smem_bytes);

    dim3 grid(Dd / TX, Hh / TY, (Ww / TZ) * 2);  // (16, 10, 10)
    compose_tile_kernel<<<grid, TPB, smem_bytes>>>(warp1, warp2, out);
}

// round 3
// speedup vs baseline: 1.1885x; 1.0238x over previous
#include <cuda_runtime.h>

// out = u2 + trilinear(u1, grid + u2), [B=2,160,160,160,3] fp32.
// Shared-memory tile for the divergent trilinear gathers; rare out-of-halo
// threads fall back to global gathers (exact same math).

#define Dd 160
#define Hh 160
#define Ww 160
#define HW  (Hh * Ww)
#define DHW (Dd * HW)

#define TX 10
#define TY 16
#define TZ 32
#define HALO 4
#define SX (TX + 2 * HALO)   // 18
#define SY (TY + 2 * HALO)   // 24
#define SZ (TZ + 2 * HALO)   // 40
#define RS (SZ * 3)          // 120 floats per (x,y) row in the tile
#define SMEM_FLOATS (SX * SY * RS)   // 51840 floats = 207,360 B
#define TPB 1024
#define NWARP (TPB / 32)     // 32
#define XPW (TX / 2)         // 5 x-slices per warp

extern __shared__ float s[];

__global__ __launch_bounds__(TPB, 1)
void compose_tile_kernel(const float* __restrict__ w1,
                         const float* __restrict__ w2,
                         float* __restrict__ out)
{
    const int x0 = blockIdx.x * TX;
    const int y0 = blockIdx.y * TY;
    const int b  = blockIdx.z / 5;
    const int z0 = (blockIdx.z % 5) * TZ;

    const int t    = threadIdx.x;
    const int lane = t & 31;
    const int wrp  = t >> 5;

    const float* __restrict__ w1b = w1 + (size_t)b * (size_t)DHW * 3;

    // ---- Cooperative tile load: w1[b, x0-4..x0+TX+3, y0-4.., z0-4..] -> smem ----
    // Row start float offset = row*480 + zlo*3; zlo % 4 == 0 always -> 16B aligned.
    {
        const int zlo  = max(z0 - HALO, 0);
        const int zhi  = min(z0 + TZ + HALO, Ww);
        const int nvec = (zhi - zlo) * 3 / 4;         // 27 or 30 float4 per row
        const int dsto = (zlo - (z0 - HALO)) * 3;     // 0 or 12 floats (16B aligned)

        for (int r = wrp; r < SX * SY; r += NWARP) {
            const int hx = r / SY;
            const int hy = r - hx * SY;
            const int cx = x0 - HALO + hx;
            const int cy = y0 - HALO + hy;
            if ((unsigned)cx < (unsigned)Dd && (unsigned)cy < (unsigned)Hh &&
                lane < nvec) {
                const float4* __restrict__ src = reinterpret_cast<const float4*>(
                    w1b + ((size_t)(cx * Hh + cy) * Ww + zlo) * 3);
                float4* dst = reinterpret_cast<float4*>(
                    s + (hx * SY + hy) * RS + dsto);
                dst[lane] = src[lane];
            }
        }
    }
    __syncthreads();

    // ---- Compute: lane = z (coalesced w2/out), warp = (y row, x half) ----
    const int hz = lane;            // 0..31
    const int hy = wrp & 15;        // 0..15
    const int xh = wrp >> 4;        // 0..1
    const int y  = y0 + hy;
    const int z  = z0 + hz;
    const int xbase = x0 + xh * XPW;

#pragma unroll
    for (int dxi = 0; dxi < XPW; ++dxi) {
        const int x = xbase + dxi;
        const int f = (((b * Dd + x) * Hh + y) * Ww + z) * 3;

        const float u2x = __ldg(w2 + f + 0);
        const float u2y = __ldg(w2 + f + 1);
        const float u2z = __ldg(w2 + f + 2);

        float lx = fminf(fmaxf((float)x + u2x, 0.0f), (float)(Dd - 1));
        float ly = fminf(fmaxf((float)y + u2y, 0.0f), (float)(Hh - 1));
        float lz = fminf(fmaxf((float)z + u2z, 0.0f), (float)(Ww - 1));

        const float fx = floorf(lx), fy = floorf(ly), fz = floorf(lz);
        const int ix0 = (int)fx, iy0 = (int)fy, iz0 = (int)fz;
        const float wx = lx - fx, wy = ly - fy, wz = lz - fz;
        const float wx0 = 1.0f - wx, wy0 = 1.0f - wy, wz0 = 1.0f - wz;

        const int ix1 = min(ix0 + 1, Dd - 1);
        const int iy1 = min(iy0 + 1, Hh - 1);
        const int iz1 = min(iz0 + 1, Ww - 1);

        const int sx0 = ix0 - (x0 - HALO);
        const int sy0 = iy0 - (y0 - HALO);
        const int sz0 = iz0 - (z0 - HALO);

        float ox, oy, oz;

        const bool fast = ((unsigned)sx0 <= (unsigned)(SX - 2)) &&
                          ((unsigned)sy0 <= (unsigned)(SY - 2)) &&
                          ((unsigned)sz0 <= (unsigned)(SZ - 2));
        if (fast) {
            const int sx1 = ix1 - (x0 - HALO);
            const int sy1 = iy1 - (y0 - HALO);
            const int za  = sz0 * 3;
            const int zb  = (iz1 - (z0 - HALO)) * 3;

            const float* p00 = s + (sx0 * SY + sy0) * RS;
            const float* p01 = s + (sx0 * SY + sy1) * RS;
            const float* p10 = s + (sx1 * SY + sy0) * RS;
            const float* p11 = s + (sx1 * SY + sy1) * RS;

            float acc[3];
#pragma unroll
            for (int c = 0; c < 3; ++c) {
                const float v00 = p00[za + c] * wz0 + p00[zb + c] * wz;
                const float v01 = p01[za + c] * wz0 + p01[zb + c] * wz;
                const float v10 = p10[za + c] * wz0 + p10[zb + c] * wz;
                const float v11 = p11[za + c] * wz0 + p11[zb + c] * wz;
                acc[c] = (v00 * wy0 + v01 * wy) * wx0 +
                         (v10 * wy0 + v11 * wy) * wx;
            }
            ox = acc[0]; oy = acc[1]; oz = acc[2];
        } else {
            // Rare slow path: direct global gather (≈0.02% of threads).
            float a0 = 0.f, a1 = 0.f, a2 = 0.f;
#pragma unroll
            for (int cx = 0; cx < 2; ++cx) {
                const int   ix  = cx ? ix1 : ix0;
                const float wxx = cx ? wx : wx0;
#pragma unroll
                for (int cy = 0; cy < 2; ++cy) {
                    const int   iy  = cy ? iy1 : iy0;
                    const float wxy = wxx * (cy ? wy : wy0);
#pragma unroll
                    for (int cz = 0; cz < 2; ++cz) {
                        const int   iz  = cz ? iz1 : iz0;
                        const float wgt = wxy * (cz ? wz : wz0);
                        const int off = ((ix * Hh + iy) * Ww + iz) * 3;
                        a0 = fmaf(__ldg(w1b + off + 0), wgt, a0);
                        a1 = fmaf(__ldg(w1b + off + 1), wgt, a1);
                        a2 = fmaf(__ldg(w1b + off + 2), wgt, a2);
                    }
                }
            }
            ox = a0; oy = a1; oz = a2;
        }

        out[f + 0] = u2x + ox;
        out[f + 1] = u2y + oy;
        out[f + 2] = u2z + oz;
    }
}

extern "C" void kernel_launch(void* const* d_in, const int* in_sizes, int n_in,
                              void* d_out, int out_size)
{
    const float* warp1 = (const float*)d_in[0];
    const float* warp2 = (const float*)d_in[1];
    float* out = (float*)d_out;

    static const size_t smem_bytes = SMEM_FLOATS * sizeof(float);  // 207,360
    cudaFuncSetAttribute(compose_tile_kernel,
                         cudaFuncAttributeMaxDynamicSharedMemorySize,
                         (int)smem_bytes);

    dim3 grid(Dd / TX, Hh / TY, (Ww / TZ) * 2);  // (16, 10, 10)
    compose_tile_kernel<<<grid, TPB, smem_bytes>>>(warp1, warp2, out);
}

// round 4
// speedup vs baseline: 1.5384x; 1.2944x over previous
#include <cuda_runtime.h>

// out = u2 + trilinear(u1, grid + u2), [B=2,160,160,160,3] fp32.
// smem tile (cp.async) for divergent gathers + software-pipelined u2 loads.

#define Dd 160
#define Hh 160
#define Ww 160
#define HW  (Hh * Ww)
#define DHW (Dd * HW)

#define TX 10
#define TY 16
#define TZ 32
#define HALO 4
#define SX (TX + 2 * HALO)   // 18
#define SY (TY + 2 * HALO)   // 24
#define SZ (TZ + 2 * HALO)   // 40
#define RS (SZ * 3)          // 120 floats per (x,y) row
#define SMEM_FLOATS (SX * SY * RS)   // 51840 floats = 207,360 B
#define TPB 1024
#define NWARP (TPB / 32)     // 32
#define XPW (TX / 2)         // 5 x-slices per warp

extern __shared__ float s[];

__device__ __forceinline__ void cp16(float* smem_dst, const float* gsrc)
{
    unsigned saddr = (unsigned)__cvta_generic_to_shared(smem_dst);
    asm volatile("cp.async.cg.shared.global [%0], [%1], 16;\n"
                 :: "r"(saddr), "l"(gsrc));
}

__global__ __launch_bounds__(TPB, 1)
void compose_tile_kernel(const float* __restrict__ w1,
                         const float* __restrict__ w2,
                         float* __restrict__ out)
{
    const int x0 = blockIdx.x * TX;
    const int y0 = blockIdx.y * TY;
    const int b  = blockIdx.z / 5;
    const int z0 = (blockIdx.z % 5) * TZ;

    const int t    = threadIdx.x;
    const int lane = t & 31;
    const int wrp  = t >> 5;

    const float* __restrict__ w1b = w1 + (size_t)b * (size_t)DHW * 3;

    // ---- Tile load via cp.async: w1[b, x0-4.., y0-4.., z0-4..] -> smem ----
    {
        const int zlo  = max(z0 - HALO, 0);
        const int zhi  = min(z0 + TZ + HALO, Ww);
        const int nvec = (zhi - zlo) * 3 / 4;         // 27 or 30 float4 per row
        const int dsto = (zlo - (z0 - HALO)) * 3;     // 16B-aligned float offset

        for (int r = wrp; r < SX * SY; r += NWARP) {
            const int hx = r / SY;
            const int hy = r - hx * SY;
            const int cx = x0 - HALO + hx;
            const int cy = y0 - HALO + hy;
            if ((unsigned)cx < (unsigned)Dd && (unsigned)cy < (unsigned)Hh &&
                lane < nvec) {
                const float* gsrc =
                    w1b + ((size_t)(cx * Hh + cy) * Ww + zlo) * 3 + lane * 4;
                float* dst = s + (hx * SY + hy) * RS + dsto + lane * 4;
                cp16(dst, gsrc);
            }
        }
        asm volatile("cp.async.commit_group;\n" ::: "memory");
    }

    // ---- Compute mapping: lane = z, warp = (y row, x half) ----
    const int hy = wrp & 15;        // 0..15
    const int xh = wrp >> 4;        // 0..1
    const int y  = y0 + hy;
    const int z  = z0 + lane;
    const int xbase = x0 + xh * XPW;

    // Prefetch first u2 while tile copies are in flight.
    const int fbase = (((b * Dd + xbase) * Hh + y) * Ww + z) * 3;
    float nu2x = __ldg(w2 + fbase + 0);
    float nu2y = __ldg(w2 + fbase + 1);
    float nu2z = __ldg(w2 + fbase + 2);

    asm volatile("cp.async.wait_group 0;\n" ::: "memory");
    __syncthreads();

#pragma unroll
    for (int dxi = 0; dxi < XPW; ++dxi) {
        const int x = xbase + dxi;
        const int f = fbase + dxi * (HW * 3);

        const float u2x = nu2x, u2y = nu2y, u2z = nu2z;
        if (dxi + 1 < XPW) {                 // prefetch next slice's u2
            nu2x = __ldg(w2 + f + HW * 3 + 0);
            nu2y = __ldg(w2 + f + HW * 3 + 1);
            nu2z = __ldg(w2 + f + HW * 3 + 2);
        }

        float lx = fminf(fmaxf((float)x + u2x, 0.0f), (float)(Dd - 1));
        float ly = fminf(fmaxf((float)y + u2y, 0.0f), (float)(Hh - 1));
        float lz = fminf(fmaxf((float)z + u2z, 0.0f), (float)(Ww - 1));

        const float fx = floorf(lx), fy = floorf(ly), fz = floorf(lz);
        const int ix0 = (int)fx, iy0 = (int)fy, iz0 = (int)fz;
        const float wx = lx - fx, wy = ly - fy, wz = lz - fz;
        const float wx0 = 1.0f - wx, wy0 = 1.0f - wy, wz0 = 1.0f - wz;

        const int ix1 = min(ix0 + 1, Dd - 1);
        const int iy1 = min(iy0 + 1, Hh - 1);
        const int iz1 = min(iz0 + 1, Ww - 1);

        const int sx0 = ix0 - (x0 - HALO);
        const int sy0 = iy0 - (y0 - HALO);
        const int sz0 = iz0 - (z0 - HALO);

        float ox, oy, oz;

        const bool fast = ((unsigned)sx0 <= (unsigned)(SX - 2)) &&
                          ((unsigned)sy0 <= (unsigned)(SY - 2)) &&
                          ((unsigned)sz0 <= (unsigned)(SZ - 2));
        if (fast) {
            const int sx1 = ix1 - (x0 - HALO);
            const int sy1 = iy1 - (y0 - HALO);
            const int za  = sz0 * 3;
            const int zb  = (iz1 - (z0 - HALO)) * 3;

            const float* p00 = s + (sx0 * SY + sy0) * RS;
            const float* p01 = s + (sx0 * SY + sy1) * RS;
            const float* p10 = s + (sx1 * SY + sy0) * RS;
            const float* p11 = s + (sx1 * SY + sy1) * RS;

            float acc[3];
#pragma unroll
            for (int c = 0; c < 3; ++c) {
                const float v00 = p00[za + c] * wz0 + p00[zb + c] * wz;
                const float v01 = p01[za + c] * wz0 + p01[zb + c] * wz;
                const float v10 = p10[za + c] * wz0 + p10[zb + c] * wz;
                const float v11 = p11[za + c] * wz0 + p11[zb + c] * wz;
                acc[c] = (v00 * wy0 + v01 * wy) * wx0 +
                         (v10 * wy0 + v11 * wy) * wx;
            }
            ox = acc[0]; oy = acc[1]; oz = acc[2];
        } else {
            // Rare slow path: direct global gather (~0.02% of threads).
            float a0 = 0.f, a1 = 0.f, a2 = 0.f;
#pragma unroll
            for (int cx = 0; cx < 2; ++cx) {
                const int   ix  = cx ? ix1 : ix0;
                const float wxx = cx ? wx : wx0;
#pragma unroll
                for (int cy = 0; cy < 2; ++cy) {
                    const int   iy  = cy ? iy1 : iy0;
                    const float wxy = wxx * (cy ? wy : wy0);
#pragma unroll
                    for (int cz = 0; cz < 2; ++cz) {
                        const int   iz  = cz ? iz1 : iz0;
                        const float wgt = wxy * (cz ? wz : wz0);
                        const int off = ((ix * Hh + iy) * Ww + iz) * 3;
                        a0 = fmaf(__ldg(w1b + off + 0), wgt, a0);
                        a1 = fmaf(__ldg(w1b + off + 1), wgt, a1);
                        a2 = fmaf(__ldg(w1b + off + 2), wgt, a2);
                    }
                }
            }
            ox = a0; oy = a1; oz = a2;
        }

        out[f + 0] = u2x + ox;
        out[f + 1] = u2y + oy;
        out[f + 2] = u2z + oz;
    }
}

extern "C" void kernel_launch(void* const* d_in, const int* in_sizes, int n_in,
                              void* d_out, int out_size)
{
    const float* warp1 = (const float*)d_in[0];
    const float* warp2 = (const float*)d_in[1];
    float* out = (float*)d_out;

    static const size_t smem_bytes = SMEM_FLOATS * sizeof(float);  // 207,360
    cudaFuncSetAttribute(compose_tile_kernel,
                         cudaFuncAttributeMaxDynamicSharedMemorySize,
                         (int)smem_bytes);

    dim3 grid(Dd / TX, Hh / TY, (Ww / TZ) * 2);  // (16, 10, 10)
    compose_tile_kernel<<<grid, TPB, smem_bytes>>>(warp1, warp2, out);
}